// round 1
// baseline (speedup 1.0000x reference)
#include <cuda_runtime.h>
#include <math.h>

#define NN 1024
#define BB 32
#define TT 12
#define HORZ 12
#define HID 64

#define BM 128
#define BN 64
#define BK 16

// ---------------- scratch (static device allocations; no cudaMalloc) ----------------
__device__ float g_S0[NN * NN];
__device__ float g_S1[NN * NN];
__device__ float g_rowsum[NN];
__device__ float g_colsum[NN];
__device__ float g_X0[NN * BB * 128];
__device__ float g_Y1a[NN * BB * 128];
__device__ float g_Y2a[NN * BB * 128];
__device__ float g_Y1b[NN * BB * 128];
__device__ float g_Y2b[NN * BB * 128];
__device__ float g_RU[NN * BB * 128];     // [N*B, 2H] sigmoid(r|u)
__device__ float g_h0[NN * BB * HID];     // layer-0 hidden (enc then dec, continued)
__device__ float g_h1[NN * BB * HID];     // layer-1 hidden
__device__ float g_xdec[NN * BB];         // decoder feedback input [N*B]

// ---------------- init ----------------
__global__ void zero_kernel() {
    int i = blockIdx.x * 256 + threadIdx.x;   // grid 8192 -> covers 2M
    if (i < NN * BB * HID) { g_h0[i] = 0.f; g_h1[i] = 0.f; }
    if (i < NN * BB) g_xdec[i] = 0.f;
}

__global__ void rowsum_kernel(const float* __restrict__ adj) {
    int n = blockIdx.x;
    float s = 0.f;
    for (int j = threadIdx.x; j < NN; j += 256) s += adj[n * NN + j];
    __shared__ float sh[256];
    sh[threadIdx.x] = s; __syncthreads();
    for (int o = 128; o; o >>= 1) {
        if (threadIdx.x < o) sh[threadIdx.x] += sh[threadIdx.x + o];
        __syncthreads();
    }
    if (threadIdx.x == 0) g_rowsum[n] = sh[0];
}

// deterministic column sums: one thread per column, coalesced across threads
__global__ void colsum_kernel(const float* __restrict__ adj) {
    int c = blockIdx.x * 256 + threadIdx.x;   // grid 4 -> 1024 cols
    float s = 0.f;
    #pragma unroll 8
    for (int r = 0; r < NN; r++) s += adj[r * NN + c];
    g_colsum[c] = s;
}

// S0[m,n] = adj[n,m]/rowsum[n] ; S1[m,n] = adj[m,n]/colsum[n]
__global__ void build_supports(const float* __restrict__ adj) {
    int idx = blockIdx.x * 256 + threadIdx.x;  // grid 4096 -> 1M
    int m = idx >> 10, n = idx & 1023;
    float rs = fmaxf(g_rowsum[n], 1e-8f);
    float cs = fmaxf(g_colsum[n], 1e-8f);
    g_S0[idx] = adj[n * NN + m] / rs;
    g_S1[idx] = adj[m * NN + n] / cs;
}

// ---------------- build X0 = concat(x, h) or concat(x, r*h) ----------------
// layout [N, B, F] flat; xKind: 0=source(enc0,t), 1=h0 (layer-1 input), 2=xdec
__global__ void concat_kernel(const float* __restrict__ src, int F, int Fx,
                              int xKind, int tstep, int useR, int hsel) {
    int idx = blockIdx.x * 256 + threadIdx.x;
    if (idx >= NN * BB * F) return;
    int f = idx % F;
    int nb = idx / F;          // n*BB + b
    float v;
    if (f < Fx) {
        if (xKind == 0) {
            int n = nb >> 5, b = nb & 31;
            v = src[((b * TT + tstep) * NN + n) * 2 + f];
        } else if (xKind == 1) {
            v = g_h0[nb * HID + f];
        } else {
            v = g_xdec[nb];
        }
    } else {
        int j = f - Fx;
        float hv = (hsel ? g_h1 : g_h0)[nb * HID + j];
        if (useR) hv *= g_RU[nb * 128 + j];   // r = first half of RU
        v = hv;
    }
    g_X0[idx] = v;
}

// ---------------- diffusion GEMM: Y = S @ X  (phase1: Y = 2*S@X - X0) ----------------
// win=0: full J (pb = bx*64, guarded by Jtot). win=1: per-batch 64-col window
// over the h-slice: pb = bx*F + Fx (in-place Chebyshev reuse of the x-part).
__global__ __launch_bounds__(256) void diffuse_kernel(int phase, int F, int Fx,
                                                      int win, int Jtot) {
    const int z = blockIdx.z;
    const float* __restrict__ S   = z ? g_S1 : g_S0;
    const float* __restrict__ Xin = (phase == 0) ? g_X0 : (z ? g_Y1b : g_Y1a);
    float* __restrict__ Yout      = (phase == 0) ? (z ? g_Y1b : g_Y1a)
                                                 : (z ? g_Y2b : g_Y2a);
    const int L = BB * F;
    int pb, wlim;
    if (win) { pb = blockIdx.x * F + Fx; wlim = 64; }
    else     { pb = blockIdx.x * BN; wlim = Jtot - pb; if (wlim > BN) wlim = BN; }
    const int mBase = blockIdx.y * BM;
    const int t = threadIdx.x;
    const int tx = t & 15, ty = t >> 4;

    __shared__ float As[BM][BK + 1];
    __shared__ float Bs[BK][BN];

    float acc[8][4];
    #pragma unroll
    for (int i = 0; i < 8; i++)
        #pragma unroll
        for (int j = 0; j < 4; j++) acc[i][j] = 0.f;

    for (int kt = 0; kt < NN; kt += BK) {
        #pragma unroll
        for (int i = 0; i < 8; i++) {
            int e = t + i * 256;
            As[e >> 4][e & 15] = S[(mBase + (e >> 4)) * NN + kt + (e & 15)];
        }
        {
            int r = t >> 4;
            int c0 = (t & 15) * 4;
            const float* xr = Xin + (kt + r) * L + pb;
            #pragma unroll
            for (int j = 0; j < 4; j++) {
                int c = c0 + j;
                Bs[r][c] = (c < wlim) ? xr[c] : 0.f;
            }
        }
        __syncthreads();
        #pragma unroll
        for (int k = 0; k < BK; k++) {
            float a[8];
            #pragma unroll
            for (int i = 0; i < 8; i++) a[i] = As[ty * 8 + i][k];
            float4 bv = *(const float4*)&Bs[k][tx * 4];
            #pragma unroll
            for (int i = 0; i < 8; i++) {
                acc[i][0] += a[i] * bv.x; acc[i][1] += a[i] * bv.y;
                acc[i][2] += a[i] * bv.z; acc[i][3] += a[i] * bv.w;
            }
        }
        __syncthreads();
    }
    #pragma unroll
    for (int i = 0; i < 8; i++) {
        int m = mBase + ty * 8 + i;
        float* yr = Yout + m * L + pb;
        const float* pr = g_X0 + m * L + pb;
        #pragma unroll
        for (int j = 0; j < 4; j++) {
            int c = tx * 4 + j;
            if (c < wlim) {
                float v = acc[i][j];
                if (phase) v = 2.f * v - pr[c];
                yr[c] = v;
            }
        }
    }
}

// ---------------- W projection: out = [X0|Y1a|Y2a|Y1b|Y2b] @ W + b ----------------
// mode 0: sigmoid -> g_RU (OUTC=128). mode 1: tanh + GRU update of h (OUTC=64).
__device__ __forceinline__ const float* zptr(int blk) {
    switch (blk) {
        case 0: return g_X0;  case 1: return g_Y1a; case 2: return g_Y2a;
        case 3: return g_Y1b; default: return g_Y2b;
    }
}

__global__ __launch_bounds__(256) void wmat_kernel(const float* __restrict__ W,
        const float* __restrict__ bias, int F, int OUTC, int mode, int hsel) {
    const int Ktot = 5 * F;
    const int rBase = blockIdx.y * BM;
    const int ob = blockIdx.x * BN;
    const int t = threadIdx.x;
    const int tx = t & 15, ty = t >> 4;

    __shared__ float As[BM][BK + 1];
    __shared__ float Bs[BK][BN];

    float acc[8][4];
    #pragma unroll
    for (int i = 0; i < 8; i++)
        #pragma unroll
        for (int j = 0; j < 4; j++) acc[i][j] = 0.f;

    for (int kt = 0; kt < Ktot; kt += BK) {
        #pragma unroll
        for (int i = 0; i < 8; i++) {
            int e = t + i * 256;
            int r = e >> 4, c = e & 15;
            int kk = kt + c;
            float v = 0.f;
            if (kk < Ktot) {
                int blk = (kk >= F) + (kk >= 2 * F) + (kk >= 3 * F) + (kk >= 4 * F);
                int f = kk - blk * F;
                v = zptr(blk)[(rBase + r) * F + f];
            }
            As[r][c] = v;
        }
        {
            int r = t >> 4, c0 = (t & 15) * 4;
            int kk = kt + r;
            const float* wr = W + kk * OUTC + ob;
            #pragma unroll
            for (int j = 0; j < 4; j++)
                Bs[r][c0 + j] = (kk < Ktot) ? wr[c0 + j] : 0.f;
        }
        __syncthreads();
        #pragma unroll
        for (int k = 0; k < BK; k++) {
            float a[8];
            #pragma unroll
            for (int i = 0; i < 8; i++) a[i] = As[ty * 8 + i][k];
            float4 bv = *(const float4*)&Bs[k][tx * 4];
            #pragma unroll
            for (int i = 0; i < 8; i++) {
                acc[i][0] += a[i] * bv.x; acc[i][1] += a[i] * bv.y;
                acc[i][2] += a[i] * bv.z; acc[i][3] += a[i] * bv.w;
            }
        }
        __syncthreads();
    }
    float* hb = hsel ? g_h1 : g_h0;
    #pragma unroll
    for (int i = 0; i < 8; i++) {
        int r = rBase + ty * 8 + i;
        #pragma unroll
        for (int j = 0; j < 4; j++) {
            int o = ob + tx * 4 + j;
            float v = acc[i][j] + bias[o];
            if (mode == 0) {
                g_RU[r * 128 + o] = 1.f / (1.f + expf(-v));
            } else {
                float cc = tanhf(v);
                float u = g_RU[r * 128 + 64 + o];
                float hv = hb[r * HID + o];
                hb[r * HID + o] = u * hv + (1.f - u) * cc;
            }
        }
    }
}

// ---------------- output projection + decoder feedback ----------------
__global__ void fcn_kernel(const float* __restrict__ fcnW,
                           const float* __restrict__ fcnb,
                           float* __restrict__ out) {
    int w = (blockIdx.x * blockDim.x + threadIdx.x) >> 5;   // row = n*BB+b
    int lane = threadIdx.x & 31;
    if (w >= NN * BB) return;
    const float* hr = g_h1 + w * HID;
    float s = hr[lane] * fcnW[lane] + hr[lane + 32] * fcnW[lane + 32];
    #pragma unroll
    for (int off = 16; off; off >>= 1) s += __shfl_down_sync(0xffffffffu, s, off);
    if (lane == 0) {
        int n = w >> 5, b = w & 31;
        float v = s + fcnb[0];
        out[b * NN + n] = v;
        g_xdec[w] = v;
    }
}

// ---------------- host orchestration ----------------
struct CellW { const float* Wru; const float* bru; const float* Wc; const float* bc; };

static void run_cell(const float* src, int xKind, int tstep, int Fx, int hsel,
                     const CellW& w) {
    int F = Fx + HID;
    int Jtot = BB * F;
    int tiles = (Jtot + BN - 1) / BN;
    int cgrid = (NN * BB * F + 255) / 256;
    // gconv for (r,u): full [x|h] diffusion
    concat_kernel<<<cgrid, 256>>>(src, F, Fx, xKind, tstep, 0, hsel);
    dim3 g1(tiles, NN / BM, 2);
    diffuse_kernel<<<g1, 256>>>(0, F, Fx, 0, Jtot);
    diffuse_kernel<<<g1, 256>>>(1, F, Fx, 0, Jtot);
    wmat_kernel<<<dim3(2, (NN * BB) / BM), 256>>>(w.Wru, w.bru, F, 128, 0, hsel);
    // gconv for c: only re-diffuse the r*h slice (x-part results reused in place)
    concat_kernel<<<cgrid, 256>>>(src, F, Fx, xKind, tstep, 1, hsel);
    dim3 g2(BB, NN / BM, 2);
    diffuse_kernel<<<g2, 256>>>(0, F, Fx, 1, Jtot);
    diffuse_kernel<<<g2, 256>>>(1, F, Fx, 1, Jtot);
    wmat_kernel<<<dim3(1, (NN * BB) / BM), 256>>>(w.Wc, w.bc, F, 64, 1, hsel);
}

extern "C" void kernel_launch(void* const* d_in, const int* in_sizes, int n_in,
                              void* d_out, int out_size) {
    (void)in_sizes; (void)n_in; (void)out_size;
    const float* adj    = (const float*)d_in[0];
    const float* source = (const float*)d_in[1];
    CellW enc0{(const float*)d_in[3],  (const float*)d_in[4],
               (const float*)d_in[5],  (const float*)d_in[6]};
    CellW enc1{(const float*)d_in[7],  (const float*)d_in[8],
               (const float*)d_in[9],  (const float*)d_in[10]};
    CellW dec0{(const float*)d_in[11], (const float*)d_in[12],
               (const float*)d_in[13], (const float*)d_in[14]};
    CellW dec1{(const float*)d_in[15], (const float*)d_in[16],
               (const float*)d_in[17], (const float*)d_in[18]};
    const float* fcnW = (const float*)d_in[19];
    const float* fcnb = (const float*)d_in[20];
    float* out = (float*)d_out;

    zero_kernel<<<8192, 256>>>();
    rowsum_kernel<<<NN, 256>>>(adj);
    colsum_kernel<<<4, 256>>>(adj);
    build_supports<<<4096, 256>>>(adj);

    // encoder: interleave the two stacked DCGRU layers per timestep
    for (int t = 0; t < TT; t++) {
        run_cell(source, 0, t, 2, 0, enc0);     // layer0: x=source[:,t], h=h0
        run_cell(source, 1, 0, HID, 1, enc1);   // layer1: x=h0(new),    h=h1
    }
    // decoder: autoregressive (teaching_force_ratio = 0)
    for (int t = 0; t < HORZ; t++) {
        run_cell(source, 2, 0, 1, 0, dec0);     // x=xdec, h=h0
        run_cell(source, 1, 0, HID, 1, dec1);   // x=h0,   h=h1
        fcn_kernel<<<4096, 256>>>(fcnW, fcnb, out + t * BB * NN);
    }
}

// round 2
// speedup vs baseline: 1.0012x; 1.0012x over previous
#include <cuda_runtime.h>
#include <math.h>

#define NN 1024
#define BB 32
#define TT 12
#define HORZ 12
#define HID 64

#define BM 128
#define BN 64
#define BK 16

// ---------------- scratch (static device allocations; no cudaMalloc) ----------------
__device__ float g_S0[NN * NN];
__device__ float g_S1[NN * NN];
__device__ float g_rowsum[NN];
__device__ float g_colsum[NN];
__device__ float g_X0[NN * BB * 128];
__device__ float g_Y1a[NN * BB * 128];
__device__ float g_Y2a[NN * BB * 128];
__device__ float g_Y1b[NN * BB * 128];
__device__ float g_Y2b[NN * BB * 128];
__device__ float g_RU[NN * BB * 128];     // [N*B, 2H] sigmoid(r|u)
__device__ float g_h0[NN * BB * HID];     // layer-0 hidden (enc then dec, continued)
__device__ float g_h1[NN * BB * HID];     // layer-1 hidden
__device__ float g_xdec[NN * BB];         // decoder feedback input [N*B]

// ---------------- init ----------------
__global__ void zero_kernel() {
    int i = blockIdx.x * 256 + threadIdx.x;   // grid 8192 -> covers 2M
    if (i < NN * BB * HID) { g_h0[i] = 0.f; g_h1[i] = 0.f; }
    if (i < NN * BB) g_xdec[i] = 0.f;
}

__global__ void rowsum_kernel(const float* __restrict__ adj) {
    int n = blockIdx.x;
    float s = 0.f;
    for (int j = threadIdx.x; j < NN; j += 256) s += adj[n * NN + j];
    __shared__ float sh[256];
    sh[threadIdx.x] = s; __syncthreads();
    for (int o = 128; o; o >>= 1) {
        if (threadIdx.x < o) sh[threadIdx.x] += sh[threadIdx.x + o];
        __syncthreads();
    }
    if (threadIdx.x == 0) g_rowsum[n] = sh[0];
}

// deterministic column sums: one thread per column, coalesced across threads
__global__ void colsum_kernel(const float* __restrict__ adj) {
    int c = blockIdx.x * 256 + threadIdx.x;   // grid 4 -> 1024 cols
    float s = 0.f;
    #pragma unroll 8
    for (int r = 0; r < NN; r++) s += adj[r * NN + c];
    g_colsum[c] = s;
}

// S0[m,n] = adj[n,m]/rowsum[n] ; S1[m,n] = adj[m,n]/colsum[n]
__global__ void build_supports(const float* __restrict__ adj) {
    int idx = blockIdx.x * 256 + threadIdx.x;  // grid 4096 -> 1M
    int m = idx >> 10, n = idx & 1023;
    float rs = fmaxf(g_rowsum[n], 1e-8f);
    float cs = fmaxf(g_colsum[n], 1e-8f);
    g_S0[idx] = adj[n * NN + m] / rs;
    g_S1[idx] = adj[m * NN + n] / cs;
}

// ---------------- build X0 = concat(x, h) or concat(x, r*h) ----------------
// layout [N, B, F] flat; xKind: 0=source(enc0,t), 1=h0 (layer-1 input), 2=xdec
__global__ void concat_kernel(const float* __restrict__ src, int F, int Fx,
                              int xKind, int tstep, int useR, int hsel) {
    int idx = blockIdx.x * 256 + threadIdx.x;
    if (idx >= NN * BB * F) return;
    int f = idx % F;
    int nb = idx / F;          // n*BB + b
    float v;
    if (f < Fx) {
        if (xKind == 0) {
            int n = nb >> 5, b = nb & 31;
            v = src[((b * TT + tstep) * NN + n) * 2 + f];
        } else if (xKind == 1) {
            v = g_h0[nb * HID + f];
        } else {
            v = g_xdec[nb];
        }
    } else {
        int j = f - Fx;
        float hv = (hsel ? g_h1 : g_h0)[nb * HID + j];
        if (useR) hv *= g_RU[nb * 128 + j];   // r = first half of RU
        v = hv;
    }
    g_X0[idx] = v;
}

// ---------------- diffusion GEMM: Y = S @ X  (phase1: Y = 2*S@X - X0) ----------------
// win=0: full J (pb = bx*64, guarded by Jtot). win=1: per-batch 64-col window
// over the h-slice: pb = bx*F + Fx (in-place Chebyshev reuse of the x-part).
__global__ __launch_bounds__(256) void diffuse_kernel(int phase, int F, int Fx,
                                                      int win, int Jtot) {
    const int z = blockIdx.z;
    const float* __restrict__ S   = z ? g_S1 : g_S0;
    const float* __restrict__ Xin = (phase == 0) ? g_X0 : (z ? g_Y1b : g_Y1a);
    float* __restrict__ Yout      = (phase == 0) ? (z ? g_Y1b : g_Y1a)
                                                 : (z ? g_Y2b : g_Y2a);
    const int L = BB * F;
    int pb, wlim;
    if (win) { pb = blockIdx.x * F + Fx; wlim = 64; }
    else     { pb = blockIdx.x * BN; wlim = Jtot - pb; if (wlim > BN) wlim = BN; }
    const int mBase = blockIdx.y * BM;
    const int t = threadIdx.x;
    const int tx = t & 15, ty = t >> 4;

    __shared__ float As[BM][BK + 1];
    __shared__ float Bs[BK][BN];

    float acc[8][4];
    #pragma unroll
    for (int i = 0; i < 8; i++)
        #pragma unroll
        for (int j = 0; j < 4; j++) acc[i][j] = 0.f;

    for (int kt = 0; kt < NN; kt += BK) {
        #pragma unroll
        for (int i = 0; i < 8; i++) {
            int e = t + i * 256;
            As[e >> 4][e & 15] = S[(mBase + (e >> 4)) * NN + kt + (e & 15)];
        }
        {
            int r = t >> 4;
            int c0 = (t & 15) * 4;
            const float* xr = Xin + (kt + r) * L + pb;
            #pragma unroll
            for (int j = 0; j < 4; j++) {
                int c = c0 + j;
                Bs[r][c] = (c < wlim) ? xr[c] : 0.f;
            }
        }
        __syncthreads();
        #pragma unroll
        for (int k = 0; k < BK; k++) {
            float a[8];
            #pragma unroll
            for (int i = 0; i < 8; i++) a[i] = As[ty * 8 + i][k];
            float4 bv = *(const float4*)&Bs[k][tx * 4];
            #pragma unroll
            for (int i = 0; i < 8; i++) {
                acc[i][0] += a[i] * bv.x; acc[i][1] += a[i] * bv.y;
                acc[i][2] += a[i] * bv.z; acc[i][3] += a[i] * bv.w;
            }
        }
        __syncthreads();
    }
    #pragma unroll
    for (int i = 0; i < 8; i++) {
        int m = mBase + ty * 8 + i;
        float* yr = Yout + m * L + pb;
        const float* pr = g_X0 + m * L + pb;
        #pragma unroll
        for (int j = 0; j < 4; j++) {
            int c = tx * 4 + j;
            if (c < wlim) {
                float v = acc[i][j];
                if (phase) v = 2.f * v - pr[c];
                yr[c] = v;
            }
        }
    }
}

// ---------------- W projection: out = [X0|Y1a|Y2a|Y1b|Y2b] @ W + b ----------------
// mode 0: sigmoid -> g_RU (OUTC=128). mode 1: tanh + GRU update of h (OUTC=64).
__device__ __forceinline__ const float* zptr(int blk) {
    switch (blk) {
        case 0: return g_X0;  case 1: return g_Y1a; case 2: return g_Y2a;
        case 3: return g_Y1b; default: return g_Y2b;
    }
}

__global__ __launch_bounds__(256) void wmat_kernel(const float* __restrict__ W,
        const float* __restrict__ bias, int F, int OUTC, int mode, int hsel) {
    const int Ktot = 5 * F;
    const int rBase = blockIdx.y * BM;
    const int ob = blockIdx.x * BN;
    const int t = threadIdx.x;
    const int tx = t & 15, ty = t >> 4;

    __shared__ float As[BM][BK + 1];
    __shared__ float Bs[BK][BN];

    float acc[8][4];
    #pragma unroll
    for (int i = 0; i < 8; i++)
        #pragma unroll
        for (int j = 0; j < 4; j++) acc[i][j] = 0.f;

    for (int kt = 0; kt < Ktot; kt += BK) {
        #pragma unroll
        for (int i = 0; i < 8; i++) {
            int e = t + i * 256;
            int r = e >> 4, c = e & 15;
            int kk = kt + c;
            float v = 0.f;
            if (kk < Ktot) {
                int blk = (kk >= F) + (kk >= 2 * F) + (kk >= 3 * F) + (kk >= 4 * F);
                int f = kk - blk * F;
                v = zptr(blk)[(rBase + r) * F + f];
            }
            As[r][c] = v;
        }
        {
            int r = t >> 4, c0 = (t & 15) * 4;
            int kk = kt + r;
            const float* wr = W + kk * OUTC + ob;
            #pragma unroll
            for (int j = 0; j < 4; j++)
                Bs[r][c0 + j] = (kk < Ktot) ? wr[c0 + j] : 0.f;
        }
        __syncthreads();
        #pragma unroll
        for (int k = 0; k < BK; k++) {
            float a[8];
            #pragma unroll
            for (int i = 0; i < 8; i++) a[i] = As[ty * 8 + i][k];
            float4 bv = *(const float4*)&Bs[k][tx * 4];
            #pragma unroll
            for (int i = 0; i < 8; i++) {
                acc[i][0] += a[i] * bv.x; acc[i][1] += a[i] * bv.y;
                acc[i][2] += a[i] * bv.z; acc[i][3] += a[i] * bv.w;
            }
        }
        __syncthreads();
    }
    float* hb = hsel ? g_h1 : g_h0;
    #pragma unroll
    for (int i = 0; i < 8; i++) {
        int r = rBase + ty * 8 + i;
        #pragma unroll
        for (int j = 0; j < 4; j++) {
            int o = ob + tx * 4 + j;
            float v = acc[i][j] + bias[o];
            if (mode == 0) {
                g_RU[r * 128 + o] = 1.f / (1.f + expf(-v));
            } else {
                float cc = tanhf(v);
                float u = g_RU[r * 128 + 64 + o];
                float hv = hb[r * HID + o];
                hb[r * HID + o] = u * hv + (1.f - u) * cc;
            }
        }
    }
}

// ---------------- output projection + decoder feedback ----------------
__global__ void fcn_kernel(const float* __restrict__ fcnW,
                           const float* __restrict__ fcnb,
                           float* __restrict__ out) {
    int w = (blockIdx.x * blockDim.x + threadIdx.x) >> 5;   // row = n*BB+b
    int lane = threadIdx.x & 31;
    if (w >= NN * BB) return;
    const float* hr = g_h1 + w * HID;
    float s = hr[lane] * fcnW[lane] + hr[lane + 32] * fcnW[lane + 32];
    #pragma unroll
    for (int off = 16; off; off >>= 1) s += __shfl_down_sync(0xffffffffu, s, off);
    if (lane == 0) {
        int n = w >> 5, b = w & 31;
        float v = s + fcnb[0];
        out[b * NN + n] = v;
        g_xdec[w] = v;
    }
}

// ---------------- host orchestration ----------------
struct CellW { const float* Wru; const float* bru; const float* Wc; const float* bc; };

static void run_cell(const float* src, int xKind, int tstep, int Fx, int hsel,
                     const CellW& w) {
    int F = Fx + HID;
    int Jtot = BB * F;
    int tiles = (Jtot + BN - 1) / BN;
    int cgrid = (NN * BB * F + 255) / 256;
    // gconv for (r,u): full [x|h] diffusion
    concat_kernel<<<cgrid, 256>>>(src, F, Fx, xKind, tstep, 0, hsel);
    dim3 g1(tiles, NN / BM, 2);
    diffuse_kernel<<<g1, 256>>>(0, F, Fx, 0, Jtot);
    diffuse_kernel<<<g1, 256>>>(1, F, Fx, 0, Jtot);
    wmat_kernel<<<dim3(2, (NN * BB) / BM), 256>>>(w.Wru, w.bru, F, 128, 0, hsel);
    // gconv for c: only re-diffuse the r*h slice (x-part results reused in place)
    concat_kernel<<<cgrid, 256>>>(src, F, Fx, xKind, tstep, 1, hsel);
    dim3 g2(BB, NN / BM, 2);
    diffuse_kernel<<<g2, 256>>>(0, F, Fx, 1, Jtot);
    diffuse_kernel<<<g2, 256>>>(1, F, Fx, 1, Jtot);
    wmat_kernel<<<dim3(1, (NN * BB) / BM), 256>>>(w.Wc, w.bc, F, 64, 1, hsel);
}

extern "C" void kernel_launch(void* const* d_in, const int* in_sizes, int n_in,
                              void* d_out, int out_size) {
    (void)in_sizes; (void)n_in; (void)out_size;
    const float* adj    = (const float*)d_in[0];
    const float* source = (const float*)d_in[1];
    CellW enc0{(const float*)d_in[3],  (const float*)d_in[4],
               (const float*)d_in[5],  (const float*)d_in[6]};
    CellW enc1{(const float*)d_in[7],  (const float*)d_in[8],
               (const float*)d_in[9],  (const float*)d_in[10]};
    CellW dec0{(const float*)d_in[11], (const float*)d_in[12],
               (const float*)d_in[13], (const float*)d_in[14]};
    CellW dec1{(const float*)d_in[15], (const float*)d_in[16],
               (const float*)d_in[17], (const float*)d_in[18]};
    const float* fcnW = (const float*)d_in[19];
    const float* fcnb = (const float*)d_in[20];
    float* out = (float*)d_out;

    zero_kernel<<<8192, 256>>>();
    rowsum_kernel<<<NN, 256>>>(adj);
    colsum_kernel<<<4, 256>>>(adj);
    build_supports<<<4096, 256>>>(adj);

    // encoder: interleave the two stacked DCGRU layers per timestep
    for (int t = 0; t < TT; t++) {
        run_cell(source, 0, t, 2, 0, enc0);     // layer0: x=source[:,t], h=h0
        run_cell(source, 1, 0, HID, 1, enc1);   // layer1: x=h0(new),    h=h1
    }
    // decoder: autoregressive (teaching_force_ratio = 0)
    for (int t = 0; t < HORZ; t++) {
        run_cell(source, 2, 0, 1, 0, dec0);     // x=xdec, h=h0
        run_cell(source, 1, 0, HID, 1, dec1);   // x=h0,   h=h1
        fcn_kernel<<<4096, 256>>>(fcnW, fcnb, out + t * BB * NN);
    }
}

// round 3
// speedup vs baseline: 2.2298x; 2.2272x over previous
#include <cuda_runtime.h>
#include <cuda_bf16.h>
#include <math.h>
#include <stdint.h>

#define NN 1024
#define BB 32
#define TT 12
#define HORZ 12
#define HID 64

#define BM 128
#define BN 64
#define BKK 64

// ---------------- scratch (static device allocations; no cudaMalloc) ----------------
__device__ float g_S0[NN * NN];
__device__ float g_S1[NN * NN];
__device__ float g_SS0[NN * NN];
__device__ float g_SS1[NN * NN];
__device__ float g_rowsum[NN];
__device__ float g_colsum[NN];
__device__ float g_X0[NN * BB * 128];
__device__ float g_Y1a[NN * BB * 128];
__device__ float g_Y2a[NN * BB * 128];
__device__ float g_Y1b[NN * BB * 128];
__device__ float g_Y2b[NN * BB * 128];
__device__ float g_RU[NN * BB * 128];
__device__ float g_h0[NN * BB * HID];
__device__ float g_h1[NN * BB * HID];
__device__ float g_xdec[NN * BB];

// bf16 hi/lo split copies of the 4 diffusion matrices (16B aligned for uint4 loads)
__device__ __align__(16) __nv_bfloat16 g_S0h[NN * NN];
__device__ __align__(16) __nv_bfloat16 g_S0l[NN * NN];
__device__ __align__(16) __nv_bfloat16 g_S1h[NN * NN];
__device__ __align__(16) __nv_bfloat16 g_S1l[NN * NN];
__device__ __align__(16) __nv_bfloat16 g_SS0h[NN * NN];
__device__ __align__(16) __nv_bfloat16 g_SS0l[NN * NN];
__device__ __align__(16) __nv_bfloat16 g_SS1h[NN * NN];
__device__ __align__(16) __nv_bfloat16 g_SS1l[NN * NN];

// ---------------- MMA helpers ----------------
__device__ __forceinline__ uint32_t smem_u32(const void* p) {
    return (uint32_t)__cvta_generic_to_shared(p);
}
__device__ __forceinline__ void ldsm4(uint32_t* r, uint32_t addr) {
    asm volatile("ldmatrix.sync.aligned.m8n8.x4.shared.b16 {%0,%1,%2,%3}, [%4];"
                 : "=r"(r[0]), "=r"(r[1]), "=r"(r[2]), "=r"(r[3]) : "r"(addr));
}
__device__ __forceinline__ void ldsm4t(uint32_t* r, uint32_t addr) {
    asm volatile("ldmatrix.sync.aligned.m8n8.x4.trans.shared.b16 {%0,%1,%2,%3}, [%4];"
                 : "=r"(r[0]), "=r"(r[1]), "=r"(r[2]), "=r"(r[3]) : "r"(addr));
}
__device__ __forceinline__ void mma16816(float* d, const uint32_t* a, const uint32_t* b) {
    asm volatile("mma.sync.aligned.m16n8k16.row.col.f32.bf16.bf16.f32 "
                 "{%0,%1,%2,%3},{%4,%5,%6,%7},{%8,%9},{%0,%1,%2,%3};"
                 : "+f"(d[0]), "+f"(d[1]), "+f"(d[2]), "+f"(d[3])
                 : "r"(a[0]), "r"(a[1]), "r"(a[2]), "r"(a[3]), "r"(b[0]), "r"(b[1]));
}
// swizzled byte offset within a tile whose rows are 64 bf16 (128B = 8 granules of 16B)
__device__ __forceinline__ uint32_t swz(int row, int g) {
    return (uint32_t)(((row << 3) + (g ^ (row & 7))) << 4);
}

union B16x8 { __nv_bfloat16 b[8]; uint4 v; };

// ---------------- init ----------------
__global__ void zero_kernel() {
    int i = blockIdx.x * 256 + threadIdx.x;
    if (i < NN * BB * HID) { g_h0[i] = 0.f; g_h1[i] = 0.f; }
    if (i < NN * BB) g_xdec[i] = 0.f;
}

__global__ void rowsum_kernel(const float* __restrict__ adj) {
    int n = blockIdx.x;
    float s = 0.f;
    for (int j = threadIdx.x; j < NN; j += 256) s += adj[n * NN + j];
    __shared__ float sh[256];
    sh[threadIdx.x] = s; __syncthreads();
    for (int o = 128; o; o >>= 1) {
        if (threadIdx.x < o) sh[threadIdx.x] += sh[threadIdx.x + o];
        __syncthreads();
    }
    if (threadIdx.x == 0) g_rowsum[n] = sh[0];
}

__global__ void colsum_kernel(const float* __restrict__ adj) {
    int c = blockIdx.x * 256 + threadIdx.x;
    float s = 0.f;
    #pragma unroll 8
    for (int r = 0; r < NN; r++) s += adj[r * NN + c];
    g_colsum[c] = s;
}

__global__ void build_supports(const float* __restrict__ adj) {
    int idx = blockIdx.x * 256 + threadIdx.x;
    int m = idx >> 10, n = idx & 1023;
    float rs = fmaxf(g_rowsum[n], 1e-8f);
    float cs = fmaxf(g_colsum[n], 1e-8f);
    g_S0[idx] = adj[n * NN + m] / rs;
    g_S1[idx] = adj[m * NN + n] / cs;
}

// fp32 -> (bf16 hi, bf16 lo)
__global__ void conv_hl(int sel) {
    int idx = blockIdx.x * 256 + threadIdx.x;
    const float* s; __nv_bfloat16 *h, *l;
    switch (sel) {
        case 0:  s = g_S0;  h = g_S0h;  l = g_S0l;  break;
        case 1:  s = g_S1;  h = g_S1h;  l = g_S1l;  break;
        case 2:  s = g_SS0; h = g_SS0h; l = g_SS0l; break;
        default: s = g_SS1; h = g_SS1h; l = g_SS1l; break;
    }
    float v = s[idx];
    __nv_bfloat16 hi = __float2bfloat16(v);
    h[idx] = hi;
    l[idx] = __float2bfloat16(v - __bfloat162float(hi));
}

// ---------------- concat (unchanged semantics) ----------------
__global__ void concat_kernel(const float* __restrict__ src, int F, int Fx,
                              int xKind, int tstep, int useR, int hsel) {
    int idx = blockIdx.x * 256 + threadIdx.x;
    if (idx >= NN * BB * F) return;
    int f = idx % F;
    int nb = idx / F;
    float v;
    if (f < Fx) {
        if (xKind == 0) {
            int n = nb >> 5, b = nb & 31;
            v = src[((b * TT + tstep) * NN + n) * 2 + f];
        } else if (xKind == 1) {
            v = g_h0[nb * HID + f];
        } else {
            v = g_xdec[nb];
        }
    } else {
        int j = f - Fx;
        float hv = (hsel ? g_h1 : g_h0)[nb * HID + j];
        if (useR) hv *= g_RU[nb * 128 + j];
        v = hv;
    }
    g_X0[idx] = v;
}

// ---------------- tensor-core diffusion GEMM ----------------
// mode 0: Y{z} = M{z} @ X0, M in {S0, SS0, S1, SS1}.  win: per-batch 64-col window.
// mode 1: SS{z} = 2 * S{z} @ S{z} - I  (z in {0,1}), B operands from bf16 S arrays.
__global__ __launch_bounds__(256) void tgemm_diffuse(int mode, int win, int F,
                                                     int Fx, int Jtot) {
    const int z = blockIdx.z;
    const __nv_bfloat16 *Ah, *Al, *Bh = 0, *Bl = 0;
    float* Yout;
    if (mode == 0) {
        switch (z) {
            case 0:  Ah = g_S0h;  Al = g_S0l;  Yout = g_Y1a; break;
            case 1:  Ah = g_SS0h; Al = g_SS0l; Yout = g_Y2a; break;
            case 2:  Ah = g_S1h;  Al = g_S1l;  Yout = g_Y1b; break;
            default: Ah = g_SS1h; Al = g_SS1l; Yout = g_Y2b; break;
        }
    } else {
        if (z == 0) { Ah = g_S0h; Al = g_S0l; Bh = g_S0h; Bl = g_S0l; Yout = g_SS0; }
        else        { Ah = g_S1h; Al = g_S1l; Bh = g_S1h; Bl = g_S1l; Yout = g_SS1; }
    }
    const int L = (mode == 1) ? NN : BB * F;
    int pb, wlim;
    if (mode == 1)      { pb = blockIdx.x * BN; wlim = BN; }
    else if (win)       { pb = blockIdx.x * F + Fx; wlim = 64; }
    else                { pb = blockIdx.x * BN; wlim = Jtot - pb; if (wlim > BN) wlim = BN; }
    const int mBase = blockIdx.y * BM;

    __shared__ __align__(16) __nv_bfloat16 Ash[BM * BKK];
    __shared__ __align__(16) __nv_bfloat16 Asl[BM * BKK];
    __shared__ __align__(16) __nv_bfloat16 Bsh[BKK * BN];
    __shared__ __align__(16) __nv_bfloat16 Bsl[BKK * BN];

    const int t = threadIdx.x;
    const int warp = t >> 5, lane = t & 31;
    const int wm = warp & 3, wn = warp >> 2;   // 4 x 2 warps, warp tile 32m x 32n

    float acc[2][4][4];
    #pragma unroll
    for (int i = 0; i < 2; i++)
        #pragma unroll
        for (int j = 0; j < 4; j++)
            #pragma unroll
            for (int k = 0; k < 4; k++) acc[i][j][k] = 0.f;

    const uint32_t sAh = smem_u32(Ash), sAl = smem_u32(Asl);
    const uint32_t sBh = smem_u32(Bsh), sBl = smem_u32(Bsl);

    for (int kt = 0; kt < NN; kt += BKK) {
        // stage A: 1024 granules of 16B, 4 per thread (direct bf16 copy)
        #pragma unroll
        for (int i = 0; i < 4; i++) {
            int gid = t + 256 * i;
            int r = gid >> 3, g = gid & 7;
            uint32_t off = swz(r, g);
            size_t gi = (size_t)(mBase + r) * NN + kt + g * 8;
            *(uint4*)((char*)Ash + off) = *(const uint4*)(Ah + gi);
            *(uint4*)((char*)Asl + off) = *(const uint4*)(Al + gi);
        }
        // stage B: 512 granules, 2 per thread
        #pragma unroll
        for (int i = 0; i < 2; i++) {
            int gid = t + 256 * i;
            int r = gid >> 3, g = gid & 7;
            uint32_t off = swz(r, g);
            if (mode == 1) {
                size_t gi = (size_t)(kt + r) * NN + pb + g * 8;
                *(uint4*)((char*)Bsh + off) = *(const uint4*)(Bh + gi);
                *(uint4*)((char*)Bsl + off) = *(const uint4*)(Bl + gi);
            } else {
                const float* xr = g_X0 + (size_t)(kt + r) * L + pb + g * 8;
                B16x8 hb, lb;
                #pragma unroll
                for (int j = 0; j < 8; j++) {
                    int c = g * 8 + j;
                    float v = (c < wlim) ? xr[j] : 0.f;
                    __nv_bfloat16 h_ = __float2bfloat16(v);
                    hb.b[j] = h_;
                    lb.b[j] = __float2bfloat16(v - __bfloat162float(h_));
                }
                *(uint4*)((char*)Bsh + off) = hb.v;
                *(uint4*)((char*)Bsl + off) = lb.v;
            }
        }
        __syncthreads();

        #pragma unroll
        for (int ks = 0; ks < BKK; ks += 16) {
            uint32_t a_h[2][4], a_l[2][4];
            #pragma unroll
            for (int ms = 0; ms < 2; ms++) {
                int row = wm * 32 + ms * 16 + (lane & 15);
                int g = (ks >> 3) + (lane >> 4);
                uint32_t off = swz(row, g);
                ldsm4(a_h[ms], sAh + off);
                ldsm4(a_l[ms], sAl + off);
            }
            uint32_t b_h[4][2], b_l[4][2];
            #pragma unroll
            for (int np = 0; np < 2; np++) {
                int row = ks + (lane & 15);
                int g = ((wn * 32 + np * 16) >> 3) + (lane >> 4);
                uint32_t off = swz(row, g);
                uint32_t r4[4];
                ldsm4t(r4, sBh + off);
                b_h[2*np][0] = r4[0]; b_h[2*np][1] = r4[1];
                b_h[2*np+1][0] = r4[2]; b_h[2*np+1][1] = r4[3];
                ldsm4t(r4, sBl + off);
                b_l[2*np][0] = r4[0]; b_l[2*np][1] = r4[1];
                b_l[2*np+1][0] = r4[2]; b_l[2*np+1][1] = r4[3];
            }
            #pragma unroll
            for (int ms = 0; ms < 2; ms++)
                #pragma unroll
                for (int ns = 0; ns < 4; ns++) {
                    mma16816(acc[ms][ns], a_h[ms], b_h[ns]);
                    mma16816(acc[ms][ns], a_h[ms], b_l[ns]);
                    mma16816(acc[ms][ns], a_l[ms], b_h[ns]);
                }
        }
        __syncthreads();
    }

    // epilogue
    #pragma unroll
    for (int ms = 0; ms < 2; ms++) {
        int row0 = mBase + wm * 32 + ms * 16 + (lane >> 2);
        #pragma unroll
        for (int ns = 0; ns < 4; ns++) {
            int col = wn * 32 + ns * 8 + (lane & 3) * 2;
            #pragma unroll
            for (int half = 0; half < 2; half++) {
                int m = row0 + half * 8;
                float v0 = acc[ms][ns][half * 2 + 0];
                float v1 = acc[ms][ns][half * 2 + 1];
                if (mode == 1) {
                    v0 = 2.f * v0 - ((m == pb + col)     ? 1.f : 0.f);
                    v1 = 2.f * v1 - ((m == pb + col + 1) ? 1.f : 0.f);
                }
                if (col < wlim)     Yout[(size_t)m * L + pb + col]     = v0;
                if (col + 1 < wlim) Yout[(size_t)m * L + pb + col + 1] = v1;
            }
        }
    }
}

// ---------------- tensor-core W projection ----------------
__device__ __forceinline__ const float* zptr(int blk) {
    switch (blk) {
        case 0: return g_X0;  case 1: return g_Y1a; case 2: return g_Y2a;
        case 3: return g_Y1b; default: return g_Y2b;
    }
}

__global__ __launch_bounds__(256) void tgemm_w(const float* __restrict__ W,
        const float* __restrict__ bias, int F, int OUTC, int mode, int hsel) {
    const int Ktot = 5 * F;
    const int rBase = blockIdx.y * BM;
    const int ob = blockIdx.x * BN;

    __shared__ __align__(16) __nv_bfloat16 Ash[BM * BKK];
    __shared__ __align__(16) __nv_bfloat16 Asl[BM * BKK];
    __shared__ __align__(16) __nv_bfloat16 Bsh[BKK * BN];
    __shared__ __align__(16) __nv_bfloat16 Bsl[BKK * BN];

    const int t = threadIdx.x;
    const int warp = t >> 5, lane = t & 31;
    const int wm = warp & 3, wn = warp >> 2;

    float acc[2][4][4];
    #pragma unroll
    for (int i = 0; i < 2; i++)
        #pragma unroll
        for (int j = 0; j < 4; j++)
            #pragma unroll
            for (int k = 0; k < 4; k++) acc[i][j][k] = 0.f;

    const uint32_t sAh = smem_u32(Ash), sAl = smem_u32(Asl);
    const uint32_t sBh = smem_u32(Bsh), sBl = smem_u32(Bsl);

    for (int kt = 0; kt < Ktot; kt += BKK) {
        // stage A: gather across the 5 concat blocks
        #pragma unroll
        for (int i = 0; i < 4; i++) {
            int gid = t + 256 * i;
            int r = gid >> 3, g = gid & 7;
            uint32_t off = swz(r, g);
            B16x8 hb, lb;
            #pragma unroll
            for (int j = 0; j < 8; j++) {
                int k = kt + g * 8 + j;
                float v = 0.f;
                if (k < Ktot) {
                    int blk = (k >= F) + (k >= 2 * F) + (k >= 3 * F) + (k >= 4 * F);
                    int f = k - blk * F;
                    v = zptr(blk)[(size_t)(rBase + r) * F + f];
                }
                __nv_bfloat16 h_ = __float2bfloat16(v);
                hb.b[j] = h_;
                lb.b[j] = __float2bfloat16(v - __bfloat162float(h_));
            }
            *(uint4*)((char*)Ash + off) = hb.v;
            *(uint4*)((char*)Asl + off) = lb.v;
        }
        // stage B from W [Ktot, OUTC]
        #pragma unroll
        for (int i = 0; i < 2; i++) {
            int gid = t + 256 * i;
            int r = gid >> 3, g = gid & 7;
            uint32_t off = swz(r, g);
            int k = kt + r;
            B16x8 hb, lb;
            #pragma unroll
            for (int j = 0; j < 8; j++) {
                float v = (k < Ktot) ? W[(size_t)k * OUTC + ob + g * 8 + j] : 0.f;
                __nv_bfloat16 h_ = __float2bfloat16(v);
                hb.b[j] = h_;
                lb.b[j] = __float2bfloat16(v - __bfloat162float(h_));
            }
            *(uint4*)((char*)Bsh + off) = hb.v;
            *(uint4*)((char*)Bsl + off) = lb.v;
        }
        __syncthreads();

        #pragma unroll
        for (int ks = 0; ks < BKK; ks += 16) {
            uint32_t a_h[2][4], a_l[2][4];
            #pragma unroll
            for (int ms = 0; ms < 2; ms++) {
                int row = wm * 32 + ms * 16 + (lane & 15);
                int g = (ks >> 3) + (lane >> 4);
                uint32_t off = swz(row, g);
                ldsm4(a_h[ms], sAh + off);
                ldsm4(a_l[ms], sAl + off);
            }
            uint32_t b_h[4][2], b_l[4][2];
            #pragma unroll
            for (int np = 0; np < 2; np++) {
                int row = ks + (lane & 15);
                int g = ((wn * 32 + np * 16) >> 3) + (lane >> 4);
                uint32_t off = swz(row, g);
                uint32_t r4[4];
                ldsm4t(r4, sBh + off);
                b_h[2*np][0] = r4[0]; b_h[2*np][1] = r4[1];
                b_h[2*np+1][0] = r4[2]; b_h[2*np+1][1] = r4[3];
                ldsm4t(r4, sBl + off);
                b_l[2*np][0] = r4[0]; b_l[2*np][1] = r4[1];
                b_l[2*np+1][0] = r4[2]; b_l[2*np+1][1] = r4[3];
            }
            #pragma unroll
            for (int ms = 0; ms < 2; ms++)
                #pragma unroll
                for (int ns = 0; ns < 4; ns++) {
                    mma16816(acc[ms][ns], a_h[ms], b_h[ns]);
                    mma16816(acc[ms][ns], a_h[ms], b_l[ns]);
                    mma16816(acc[ms][ns], a_l[ms], b_h[ns]);
                }
        }
        __syncthreads();
    }

    float* hb_ = hsel ? g_h1 : g_h0;
    #pragma unroll
    for (int ms = 0; ms < 2; ms++) {
        int row0 = rBase + wm * 32 + ms * 16 + (lane >> 2);
        #pragma unroll
        for (int ns = 0; ns < 4; ns++) {
            int colb = wn * 32 + ns * 8 + (lane & 3) * 2;
            #pragma unroll
            for (int half = 0; half < 2; half++) {
                int r = row0 + half * 8;
                #pragma unroll
                for (int q = 0; q < 2; q++) {
                    int o = ob + colb + q;
                    float v = acc[ms][ns][half * 2 + q] + bias[o];
                    if (mode == 0) {
                        g_RU[(size_t)r * 128 + o] = 1.f / (1.f + expf(-v));
                    } else {
                        float cc = tanhf(v);
                        float u = g_RU[(size_t)r * 128 + 64 + o];
                        float hv = hb_[(size_t)r * HID + o];
                        hb_[(size_t)r * HID + o] = u * hv + (1.f - u) * cc;
                    }
                }
            }
        }
    }
}

// ---------------- output projection + decoder feedback ----------------
__global__ void fcn_kernel(const float* __restrict__ fcnW,
                           const float* __restrict__ fcnb,
                           float* __restrict__ out) {
    int w = (blockIdx.x * blockDim.x + threadIdx.x) >> 5;
    int lane = threadIdx.x & 31;
    if (w >= NN * BB) return;
    const float* hr = g_h1 + (size_t)w * HID;
    float s = hr[lane] * fcnW[lane] + hr[lane + 32] * fcnW[lane + 32];
    #pragma unroll
    for (int off = 16; off; off >>= 1) s += __shfl_down_sync(0xffffffffu, s, off);
    if (lane == 0) {
        int n = w >> 5, b = w & 31;
        float v = s + fcnb[0];
        out[b * NN + n] = v;
        g_xdec[w] = v;
    }
}

// ---------------- host orchestration ----------------
struct CellW { const float* Wru; const float* bru; const float* Wc; const float* bc; };

static void run_cell(const float* src, int xKind, int tstep, int Fx, int hsel,
                     const CellW& w) {
    int F = Fx + HID;
    int Jtot = BB * F;
    int tiles = (Jtot + BN - 1) / BN;
    int cgrid = (NN * BB * F + 255) / 256;
    concat_kernel<<<cgrid, 256>>>(src, F, Fx, xKind, tstep, 0, hsel);
    tgemm_diffuse<<<dim3(tiles, NN / BM, 4), 256>>>(0, 0, F, Fx, Jtot);
    tgemm_w<<<dim3(2, (NN * BB) / BM), 256>>>(w.Wru, w.bru, F, 128, 0, hsel);
    concat_kernel<<<cgrid, 256>>>(src, F, Fx, xKind, tstep, 1, hsel);
    tgemm_diffuse<<<dim3(BB, NN / BM, 4), 256>>>(0, 1, F, Fx, Jtot);
    tgemm_w<<<dim3(1, (NN * BB) / BM), 256>>>(w.Wc, w.bc, F, 64, 1, hsel);
}

extern "C" void kernel_launch(void* const* d_in, const int* in_sizes, int n_in,
                              void* d_out, int out_size) {
    (void)in_sizes; (void)n_in; (void)out_size;
    const float* adj    = (const float*)d_in[0];
    const float* source = (const float*)d_in[1];
    CellW enc0{(const float*)d_in[3],  (const float*)d_in[4],
               (const float*)d_in[5],  (const float*)d_in[6]};
    CellW enc1{(const float*)d_in[7],  (const float*)d_in[8],
               (const float*)d_in[9],  (const float*)d_in[10]};
    CellW dec0{(const float*)d_in[11], (const float*)d_in[12],
               (const float*)d_in[13], (const float*)d_in[14]};
    CellW dec1{(const float*)d_in[15], (const float*)d_in[16],
               (const float*)d_in[17], (const float*)d_in[18]};
    const float* fcnW = (const float*)d_in[19];
    const float* fcnb = (const float*)d_in[20];
    float* out = (float*)d_out;

    zero_kernel<<<8192, 256>>>();
    rowsum_kernel<<<NN, 256>>>(adj);
    colsum_kernel<<<4, 256>>>(adj);
    build_supports<<<4096, 256>>>(adj);
    conv_hl<<<4096, 256>>>(0);
    conv_hl<<<4096, 256>>>(1);
    // SS{z} = 2 * S{z}^2 - I  via the tensor GEMM itself
    tgemm_diffuse<<<dim3(NN / BN, NN / BM, 2), 256>>>(1, 0, 0, 0, NN);
    conv_hl<<<4096, 256>>>(2);
    conv_hl<<<4096, 256>>>(3);

    for (int t = 0; t < TT; t++) {
        run_cell(source, 0, t, 2, 0, enc0);
        run_cell(source, 1, 0, HID, 1, enc1);
    }
    for (int t = 0; t < HORZ; t++) {
        run_cell(source, 2, 0, 1, 0, dec0);
        run_cell(source, 1, 0, HID, 1, dec1);
        fcn_kernel<<<4096, 256>>>(fcnW, fcnb, out + t * BB * NN);
    }
}